// round 1
// baseline (speedup 1.0000x reference)
#include <cuda_runtime.h>

// Problem constants (fixed shapes)
#define BQ   4
#define KC   24
#define DD   16
#define NPIX (512 * 1024)
#define KP   17              // padded stride: 17 coprime with 32 -> distinct banks per label

// ---------------- device scratch (no allocations allowed) ----------------
__device__ float g_sums[BQ * KC * DD];
__device__ float g_counts[BQ * KC];
__device__ float g_centers[BQ * KC * DD];
__device__ float g_var[BQ * KC];
__device__ float g_extra;   // dist + reg contribution

// ---------------- init: zero accumulators ----------------
__global__ void k_init() {
    int t = blockIdx.x * blockDim.x + threadIdx.x;
    if (t < BQ * KC * DD) g_sums[t] = 0.f;
    if (t < BQ * KC) { g_counts[t] = 0.f; g_var[t] = 0.f; }
}

// ---------------- pass 1: per-cluster sums + counts ----------------
// grid = (NPIX / 2048, BQ), block = 256. Each thread handles 2 x int4/float4
// vectors = 8 points. Data loads are float4 coalesced along pixel dim.
__global__ void __launch_bounds__(256) k_accum(const float* __restrict__ data,
                                               const int*  __restrict__ labels) {
    __shared__ float s_sums[KC * KP];
    __shared__ float s_cnt[KC];
    const int t = threadIdx.x;
    for (int i = t; i < KC * KP; i += 256) s_sums[i] = 0.f;
    if (t < KC) s_cnt[t] = 0.f;
    __syncthreads();

    const int b = blockIdx.y;
    const float* dptr = data + (size_t)b * DD * NPIX;
    const int*   lptr = labels + (size_t)b * NPIX;

    const int vbase = blockIdx.x * (256 * 2);
#pragma unroll
    for (int it = 0; it < 2; it++) {
        const int vn = vbase + it * 256 + t;     // float4 index
        const int4 l4 = reinterpret_cast<const int4*>(lptr)[vn];
        atomicAdd(&s_cnt[l4.x], 1.f);
        atomicAdd(&s_cnt[l4.y], 1.f);
        atomicAdd(&s_cnt[l4.z], 1.f);
        atomicAdd(&s_cnt[l4.w], 1.f);
        const int o0 = l4.x * KP, o1 = l4.y * KP, o2 = l4.z * KP, o3 = l4.w * KP;
#pragma unroll
        for (int d = 0; d < DD; d++) {
            const float4 v =
                reinterpret_cast<const float4*>(dptr + (size_t)d * NPIX)[vn];
            atomicAdd(&s_sums[o0 + d], v.x);
            atomicAdd(&s_sums[o1 + d], v.y);
            atomicAdd(&s_sums[o2 + d], v.z);
            atomicAdd(&s_sums[o3 + d], v.w);
        }
    }
    __syncthreads();

    for (int i = t; i < KC * DD; i += 256) {
        const int k = i >> 4, d = i & 15;
        atomicAdd(&g_sums[(b * KC + k) * DD + d], s_sums[k * KP + d]);
    }
    if (t < KC) atomicAdd(&g_counts[b * KC + t], s_cnt[t]);
}

// ---------------- centers + pairwise-dist term + reg term ----------------
// single block, 256 threads
__global__ void k_centers() {
    __shared__ float s_c[BQ * KC * DD];
    __shared__ float s_red[256];
    const int t = threadIdx.x;

    for (int i = t; i < BQ * KC * DD; i += 256) {
        const float c = g_sums[i] / g_counts[i >> 4];
        s_c[i] = c;
        g_centers[i] = c;
    }
    __syncthreads();

    const float inv_pairs = 1.f / (2.f * KC * (KC - 1));
    float acc = 0.f;
    // pairwise hinge distances (diagonal kept: cd=0 -> (2-0)^2, as in reference)
    for (int i = t; i < BQ * KC * KC; i += 256) {
        const int b = i / (KC * KC);
        const int r = i - b * KC * KC;
        const int k1 = r / KC, k2 = r - k1 * KC;
        const float* c1 = &s_c[(b * KC + k1) * DD];
        const float* c2 = &s_c[(b * KC + k2) * DD];
        float sq = 0.f;
#pragma unroll
        for (int d = 0; d < DD; d++) { const float df = c1[d] - c2[d]; sq += df * df; }
        const float cd = (k1 == k2) ? 0.f : sqrtf(sq);
        const float h  = fmaxf(2.f - cd, 0.f);
        acc += h * h * inv_pairs;
    }
    // regularization: mean center norm per image, summed over batch
    for (int i = t; i < BQ * KC; i += 256) {
        const float* c = &s_c[i * DD];
        float sq = 0.f;
#pragma unroll
        for (int d = 0; d < DD; d++) sq += c[d] * c[d];
        acc += sqrtf(sq) * (1.f / KC);
    }

    s_red[t] = acc;
    __syncthreads();
    for (int s = 128; s > 0; s >>= 1) {
        if (t < s) s_red[t] += s_red[t + s];
        __syncthreads();
    }
    if (t == 0) g_extra = s_red[0];
}

// ---------------- pass 2: hinged variance per cluster ----------------
__global__ void __launch_bounds__(256) k_var(const float* __restrict__ data,
                                             const int*  __restrict__ labels) {
    __shared__ float s_c[KC * KP];
    __shared__ float s_v[KC];
    const int t = threadIdx.x;
    const int b = blockIdx.y;

    for (int i = t; i < KC * DD; i += 256)
        s_c[(i >> 4) * KP + (i & 15)] = g_centers[b * KC * DD + i];
    if (t < KC) s_v[t] = 0.f;
    __syncthreads();

    const float* dptr = data + (size_t)b * DD * NPIX;
    const int*   lptr = labels + (size_t)b * NPIX;

    const int vbase = blockIdx.x * (256 * 2);
#pragma unroll
    for (int it = 0; it < 2; it++) {
        const int vn = vbase + it * 256 + t;
        const int4 l4 = reinterpret_cast<const int4*>(lptr)[vn];
        const int o0 = l4.x * KP, o1 = l4.y * KP, o2 = l4.z * KP, o3 = l4.w * KP;
        float s0 = 0.f, s1 = 0.f, s2 = 0.f, s3 = 0.f;
#pragma unroll
        for (int d = 0; d < DD; d++) {
            const float4 v =
                reinterpret_cast<const float4*>(dptr + (size_t)d * NPIX)[vn];
            const float a0 = v.x - s_c[o0 + d]; s0 += a0 * a0;
            const float a1 = v.y - s_c[o1 + d]; s1 += a1 * a1;
            const float a2 = v.z - s_c[o2 + d]; s2 += a2 * a2;
            const float a3 = v.w - s_c[o3 + d]; s3 += a3 * a3;
        }
        const float h0 = fmaxf(sqrtf(s0) - 1.f, 0.f);
        const float h1 = fmaxf(sqrtf(s1) - 1.f, 0.f);
        const float h2 = fmaxf(sqrtf(s2) - 1.f, 0.f);
        const float h3 = fmaxf(sqrtf(s3) - 1.f, 0.f);
        atomicAdd(&s_v[l4.x], h0 * h0);
        atomicAdd(&s_v[l4.y], h1 * h1);
        atomicAdd(&s_v[l4.z], h2 * h2);
        atomicAdd(&s_v[l4.w], h3 * h3);
    }
    __syncthreads();
    if (t < KC) atomicAdd(&g_var[b * KC + t], s_v[t]);
}

// ---------------- finalize ----------------
__global__ void k_final(float* __restrict__ out) {
    __shared__ float s_red[128];
    const int t = threadIdx.x;
    float v = 0.f;
    if (t < BQ * KC) v = g_var[t] / g_counts[t];
    s_red[t] = v;
    __syncthreads();
    for (int s = 64; s > 0; s >>= 1) {
        if (t < s) s_red[t] += s_red[t + s];
        __syncthreads();
    }
    if (t == 0) out[0] = (s_red[0] + g_extra) * (1.f / BQ);
}

// ---------------- entry point ----------------
extern "C" void kernel_launch(void* const* d_in, const int* in_sizes, int n_in,
                              void* d_out, int out_size) {
    const float* data   = (const float*)d_in[0];
    const int*   labels = (const int*)d_in[1];
    float* out = (float*)d_out;

    k_init<<<6, 256>>>();

    dim3 grid(NPIX / 2048, BQ);
    k_accum<<<grid, 256>>>(data, labels);

    k_centers<<<1, 256>>>();

    k_var<<<grid, 256>>>(data, labels);

    k_final<<<1, 128>>>(out);
}

// round 2
// speedup vs baseline: 1.2068x; 1.2068x over previous
#include <cuda_runtime.h>

// Problem constants (fixed shapes)
#define BQ   4
#define KC   24
#define DD   16
#define NPIX (512 * 1024)
#define KP   17

// k_accum tiling
#define TILE      512          // points per tile
#define SROW      513          // smem row stride (odd -> 16 distinct banks for lane*SROW)
#define TILES_PB  4            // tiles per block
#define ABLOCKS   (NPIX / TILE / TILES_PB)   // 256 blocks per batch image

// ---------------- device scratch ----------------
__device__ float g_sums[BQ * KC * DD];
__device__ float g_counts[BQ * KC];
__device__ float g_centers[BQ * KC * DD];
__device__ float g_invc[BQ * KC];
__device__ float g_vtot;
__device__ float g_extra;

// ---------------- init ----------------
__global__ void k_init() {
    int t = blockIdx.x * blockDim.x + threadIdx.x;
    if (t < BQ * KC * DD) g_sums[t] = 0.f;
    if (t < BQ * KC) g_counts[t] = 0.f;
    if (t == 0) g_vtot = 0.f;
}

// ---------------- pass 1: per-cluster sums + counts (atomic-free hot loop) ----
// Tile of 512 points staged into smem as s_data[d][col], col = ((q&3)<<7)|(q>>2)
// where q = pixel-in-tile. Each warp owns 3 clusters; ballot-scan labels, gather
// matched points' 16 dims into register accumulators (lane = dim).
__global__ void __launch_bounds__(256) k_accum(const float* __restrict__ data,
                                               const int*  __restrict__ labels) {
    __shared__ float s_data[DD * SROW];
    __shared__ int   s_lab[TILE];

    const int t = threadIdx.x;
    const int w = t >> 5;
    const int lane = t & 31;
    const int b = blockIdx.y;
    const float* dptr = data + (size_t)b * DD * NPIX;
    const int*   lptr = labels + (size_t)b * NPIX;

    const int c0 = w * 3, c1 = c0 + 1, c2 = c0 + 2;
    float a0 = 0.f, a1 = 0.f, a2 = 0.f;
    float n0 = 0.f, n1 = 0.f, n2 = 0.f;

    const float* myrow = &s_data[(lane & 15) * SROW];

    for (int ti = 0; ti < TILES_PB; ti++) {
        const int tile = blockIdx.x * TILES_PB + ti;
        const int p4base = tile * (TILE / 4);   // float4 index base

        // ---- stage 1: labels + data into smem ----
        if (t < TILE / 4) {
            const int4 l4 = reinterpret_cast<const int4*>(lptr)[p4base + t];
            s_lab[t * 4 + 0] = l4.x;
            s_lab[t * 4 + 1] = l4.y;
            s_lab[t * 4 + 2] = l4.z;
            s_lab[t * 4 + 3] = l4.w;
        }
#pragma unroll
        for (int i = 0; i < 8; i++) {
            const int idx = t + i * 256;         // 0..2047
            const int d = idx >> 7;
            const int pv = idx & 127;            // float4 within row
            const float4 v =
                reinterpret_cast<const float4*>(dptr + (size_t)d * NPIX)[p4base + pv];
            float* row = &s_data[d * SROW];
            row[pv]       = v.x;                 // q=4pv+0 -> col 0*128+pv
            row[128 + pv] = v.y;
            row[256 + pv] = v.z;
            row[384 + pv] = v.w;
        }
        __syncthreads();

        // ---- stage 2: ballot-scan + gather ----
#pragma unroll 4
        for (int ch = 0; ch < TILE / 32; ch++) {
            const int lab = s_lab[ch * 32 + lane];
            unsigned m0 = __ballot_sync(0xffffffffu, lab == c0);
            unsigned m1 = __ballot_sync(0xffffffffu, lab == c1);
            unsigned m2 = __ballot_sync(0xffffffffu, lab == c2);
            n0 += (float)__popc(m0);
            n1 += (float)__popc(m1);
            n2 += (float)__popc(m2);
            const int basep = ch * 32;

#define GATHER(mask, acc)                                                      \
            while (mask) {                                                     \
                int p0 = __ffs(mask) - 1; mask &= mask - 1;                    \
                int p1 = p0;                                                   \
                bool two = (mask != 0);                                        \
                if (two) { p1 = __ffs(mask) - 1; mask &= mask - 1; }           \
                const int q = basep + ((lane < 16) ? p0 : p1);                 \
                const int col = ((q & 3) << 7) | (q >> 2);                     \
                const float v = myrow[col];                                    \
                if (two || lane < 16) acc += v;                                \
            }

            GATHER(m0, a0)
            GATHER(m1, a1)
            GATHER(m2, a2)
#undef GATHER
        }
        __syncthreads();
    }

    // fold high half (second point of dual gather) into low half
    a0 += __shfl_xor_sync(0xffffffffu, a0, 16);
    a1 += __shfl_xor_sync(0xffffffffu, a1, 16);
    a2 += __shfl_xor_sync(0xffffffffu, a2, 16);

    if (lane < 16) {
        atomicAdd(&g_sums[(b * KC + c0) * DD + lane], a0);
        atomicAdd(&g_sums[(b * KC + c1) * DD + lane], a1);
        atomicAdd(&g_sums[(b * KC + c2) * DD + lane], a2);
    }
    if (lane == 0) {
        atomicAdd(&g_counts[b * KC + c0], n0);
        atomicAdd(&g_counts[b * KC + c1], n1);
        atomicAdd(&g_counts[b * KC + c2], n2);
    }
}

// ---------------- centers + dist term + reg term + inv counts ----------------
__global__ void k_centers() {
    __shared__ float s_c[BQ * KC * DD];
    __shared__ float s_red[256];
    const int t = threadIdx.x;

    for (int i = t; i < BQ * KC * DD; i += 256) {
        const float c = g_sums[i] / g_counts[i >> 4];
        s_c[i] = c;
        g_centers[i] = c;
    }
    if (t < BQ * KC) g_invc[t] = 1.f / g_counts[t];
    __syncthreads();

    const float inv_pairs = 1.f / (2.f * KC * (KC - 1));
    float acc = 0.f;
    for (int i = t; i < BQ * KC * KC; i += 256) {
        const int b = i / (KC * KC);
        const int r = i - b * KC * KC;
        const int k1 = r / KC, k2 = r - k1 * KC;
        const float* c1 = &s_c[(b * KC + k1) * DD];
        const float* c2 = &s_c[(b * KC + k2) * DD];
        float sq = 0.f;
#pragma unroll
        for (int d = 0; d < DD; d++) { const float df = c1[d] - c2[d]; sq += df * df; }
        const float cd = (k1 == k2) ? 0.f : sqrtf(sq);
        const float h  = fmaxf(2.f - cd, 0.f);
        acc += h * h * inv_pairs;
    }
    for (int i = t; i < BQ * KC; i += 256) {
        const float* c = &s_c[i * DD];
        float sq = 0.f;
#pragma unroll
        for (int d = 0; d < DD; d++) sq += c[d] * c[d];
        acc += sqrtf(sq) * (1.f / KC);
    }

    s_red[t] = acc;
    __syncthreads();
    for (int s = 128; s > 0; s >>= 1) {
        if (t < s) s_red[t] += s_red[t + s];
        __syncthreads();
    }
    if (t == 0) g_extra = s_red[0];
}

// ---------------- pass 2: hinged variance, atomic-free (weighted by 1/count) --
__global__ void __launch_bounds__(256) k_var(const float* __restrict__ data,
                                             const int*  __restrict__ labels) {
    __shared__ float s_c[KC * KP];
    __shared__ float s_ic[KC];
    __shared__ float s_red[8];
    const int t = threadIdx.x;
    const int b = blockIdx.y;

    for (int i = t; i < KC * DD; i += 256)
        s_c[(i >> 4) * KP + (i & 15)] = g_centers[b * KC * DD + i];
    if (t < KC) s_ic[t] = g_invc[b * KC + t];
    __syncthreads();

    const float* dptr = data + (size_t)b * DD * NPIX;
    const int*   lptr = labels + (size_t)b * NPIX;

    // reversed block order: start where pass 1 ended -> L2 reuse
    const int bx = gridDim.x - 1 - blockIdx.x;
    const int vbase = bx * (256 * 2);

    float acc = 0.f;
#pragma unroll
    for (int it = 0; it < 2; it++) {
        const int vn = vbase + it * 256 + t;
        const int4 l4 = reinterpret_cast<const int4*>(lptr)[vn];
        const int o0 = l4.x * KP, o1 = l4.y * KP, o2 = l4.z * KP, o3 = l4.w * KP;
        float s0 = 0.f, s1 = 0.f, s2 = 0.f, s3 = 0.f;
#pragma unroll
        for (int d = 0; d < DD; d++) {
            const float4 v =
                reinterpret_cast<const float4*>(dptr + (size_t)d * NPIX)[vn];
            const float a0 = v.x - s_c[o0 + d]; s0 += a0 * a0;
            const float a1 = v.y - s_c[o1 + d]; s1 += a1 * a1;
            const float a2 = v.z - s_c[o2 + d]; s2 += a2 * a2;
            const float a3 = v.w - s_c[o3 + d]; s3 += a3 * a3;
        }
        const float h0 = fmaxf(sqrtf(s0) - 1.f, 0.f);
        const float h1 = fmaxf(sqrtf(s1) - 1.f, 0.f);
        const float h2 = fmaxf(sqrtf(s2) - 1.f, 0.f);
        const float h3 = fmaxf(sqrtf(s3) - 1.f, 0.f);
        acc += h0 * h0 * s_ic[l4.x];
        acc += h1 * h1 * s_ic[l4.y];
        acc += h2 * h2 * s_ic[l4.z];
        acc += h3 * h3 * s_ic[l4.w];
    }

    // warp reduce, then block reduce, one global atomic per block
#pragma unroll
    for (int o = 16; o > 0; o >>= 1)
        acc += __shfl_xor_sync(0xffffffffu, acc, o);
    if ((t & 31) == 0) s_red[t >> 5] = acc;
    __syncthreads();
    if (t < 8) {
        float v = s_red[t];
#pragma unroll
        for (int o = 4; o > 0; o >>= 1)
            v += __shfl_xor_sync(0xffu, v, o);
        if (t == 0) atomicAdd(&g_vtot, v);
    }
}

// ---------------- finalize ----------------
__global__ void k_final(float* __restrict__ out) {
    if (threadIdx.x == 0)
        out[0] = (g_vtot + g_extra) * (1.f / BQ);
}

// ---------------- entry point ----------------
extern "C" void kernel_launch(void* const* d_in, const int* in_sizes, int n_in,
                              void* d_out, int out_size) {
    const float* data   = (const float*)d_in[0];
    const int*   labels = (const int*)d_in[1];
    float* out = (float*)d_out;

    k_init<<<6, 256>>>();

    dim3 agrid(ABLOCKS, BQ);
    k_accum<<<agrid, 256>>>(data, labels);

    k_centers<<<1, 256>>>();

    dim3 vgrid(NPIX / 2048, BQ);
    k_var<<<vgrid, 256>>>(data, labels);

    k_final<<<1, 32>>>(out);
}